// round 15
// baseline (speedup 1.0000x reference)
#include <cuda_runtime.h>
#include <cuda_fp16.h>
#include <math.h>
#include <stdint.h>

#define NN 10000
#define NE 30000
#define NG 50
#define HH 8
#define NTOT1 12800  // 3*4096+512

// ---------------- scratch (device globals) ----------------
__device__ __half g_qkvs[NN * NTOT1];
__device__ float g_hA[NN * 512];
__device__ float g_gate[NN];
__device__ float g_biasp[NTOT1];
__device__ __half g_Acomp[NN * 512];
__device__ __half g_Bcomp[6400 * 512];
__device__ int g_deg[NN];
__device__ int g_rowptr[NN + 1];
__device__ int g_cursor[NN];
__device__ int g_psrc[NE];   // src node id per CSR slot

// ---------------- helpers ----------------
__device__ __forceinline__ uint32_t smem_u32(const void* p) {
    uint32_t a;
    asm("{ .reg .u64 t; cvta.to.shared.u64 t, %1; cvt.u32.u64 %0, t; }" : "=r"(a) : "l"(p));
    return a;
}
__device__ __forceinline__ void cp16(uint32_t saddr, const void* g, bool pred) {
    int sz = pred ? 16 : 0;
    asm volatile("cp.async.cg.shared.global [%0], [%1], 16, %2;" :: "r"(saddr), "l"(g), "r"(sz));
}
__device__ __forceinline__ void cp_commit() { asm volatile("cp.async.commit_group;"); }
__device__ __forceinline__ void cp_wait0() { asm volatile("cp.async.wait_group 0;"); }
__device__ __forceinline__ void ldmx4(uint32_t* r, uint32_t addr) {
    asm volatile("ldmatrix.sync.aligned.m8n8.x4.shared.b16 {%0,%1,%2,%3}, [%4];"
                 : "=r"(r[0]), "=r"(r[1]), "=r"(r[2]), "=r"(r[3]) : "r"(addr));
}
__device__ __forceinline__ void mma_fp16(float* c, const uint32_t* a, uint32_t b0, uint32_t b1) {
    asm volatile(
        "mma.sync.aligned.m16n8k16.row.col.f32.f16.f16.f32 "
        "{%0,%1,%2,%3}, {%4,%5,%6,%7}, {%8,%9}, {%0,%1,%2,%3};"
        : "+f"(c[0]), "+f"(c[1]), "+f"(c[2]), "+f"(c[3])
        : "r"(a[0]), "r"(a[1]), "r"(a[2]), "r"(a[3]), "r"(b0), "r"(b1));
}
__device__ __forceinline__ void h8_to_f8(uint4 t, float* f) {
    const __half2* hp = (const __half2*)&t;
#pragma unroll
    for (int j = 0; j < 4; j++) {
        float2 xy = __half22float2(hp[j]);
        f[2 * j] = xy.x;
        f[2 * j + 1] = xy.y;
    }
}
__device__ __forceinline__ int lbound(const int* a, int n, int key) {
    int lo = 0, hi = n;
    while (lo < hi) {
        int mid = (lo + hi) >> 1;
        if (a[mid] < key) lo = mid + 1;
        else hi = mid;
    }
    return lo;
}

// ---------------- utility kernels ----------------
__global__ void fill_int_kernel(int* p, int v, int n) {
    int i = blockIdx.x * blockDim.x + threadIdx.x;
    if (i < n) p[i] = v;
}

// ---------------- fp32 -> fp16 convert ----------------
__global__ void convA_kernel(const float* __restrict__ A, __half* __restrict__ out, size_t n) {
    size_t i = (size_t)blockIdx.x * blockDim.x + threadIdx.x;
    if (i >= n) return;
    out[i] = __float2half_rn(A[i]);
}

__global__ void convBT4_kernel(const float* __restrict__ qw, const float* __restrict__ kw,
                               const float* __restrict__ vw, const float* __restrict__ sw,
                               __half* __restrict__ out, int K, int hc, int C) {
    int z = blockIdx.z;
    const float* W = (z == 0) ? qw : (z == 1) ? kw : (z == 2) ? vw : sw;
    int N = (z < 3) ? hc : C;
    int rowOff = z * hc;
    __shared__ float t[32][33];
    int kb = blockIdx.x * 32, nb = blockIdx.y * 32;
    if (nb >= N) return;
    int tx = threadIdx.x, ty = threadIdx.y;  // 32 x 8
    for (int r = ty; r < 32; r += 8) {
        int kk = kb + r, nn2 = nb + tx;
        t[r][tx] = (kk < K && nn2 < N) ? W[(size_t)kk * N + nn2] : 0.f;
    }
    __syncthreads();
    for (int r = ty; r < 32; r += 8) {
        int nn2 = nb + r, kk = kb + tx;
        if (nn2 < N && kk < K)
            out[(size_t)(rowOff + nn2) * K + kk] = __float2half_rn(t[tx][r]);
    }
}

__global__ void pack_bias_kernel(const float* __restrict__ qb, const float* __restrict__ kb,
                                 const float* __restrict__ vb, const float* __restrict__ sb,
                                 int hc, int C, float* __restrict__ out) {
    int i = blockIdx.x * blockDim.x + threadIdx.x;
    int Ntot = 3 * hc + C;
    if (i >= Ntot) return;
    float v;
    if (i < hc) v = qb[i];
    else if (i < 2 * hc) v = kb[i - hc];
    else if (i < 3 * hc) v = vb[i - 2 * hc];
    else v = sb[i - 3 * hc];
    out[i] = v;
}

// ---------------- fp16 mma.sync GEMM: 64x128 tile, 8 warps (2x4, 32x32 each), 3 CTAs/SM ----------------
#define BM 64
#define BN 128
#define BKK 64
#define LDT 72
#define SA_BYTES (BM * LDT * 2)
#define SB_BYTES (BN * LDT * 2)
#define GEMM_SMEM (2 * (SA_BYTES + SB_BYTES))

__global__ void __launch_bounds__(256, 3)
gemm_mma_kernel(const __half* __restrict__ A, const __half* __restrict__ B,
                const float* __restrict__ bias, __half* __restrict__ C,
                int M, int K, int N) {
    extern __shared__ char smraw[];
    uint32_t aBase = smem_u32(smraw);
    uint32_t bBase = aBase + 2 * SA_BYTES;
    int tid = threadIdx.x;
    int lane = tid & 31, wid = tid >> 5;
    int m0 = blockIdx.y * BM, n0 = blockIdx.x * BN;
    int warp_m = wid & 1, warp_n = wid >> 1;  // 2 x 4
    int m_base = warp_m * 32, n_base = warp_n * 32;

    float acc[2][4][4];
#pragma unroll
    for (int i = 0; i < 2; i++)
#pragma unroll
        for (int j = 0; j < 4; j++)
#pragma unroll
            for (int r = 0; r < 4; r++) acc[i][j][r] = 0.f;

    int nk = K >> 6;  // K multiple of 64

    auto load_stage = [&](int st, int kt) {
        // A: 64 rows x 8 chunks = 512 tasks (2/thread)
#pragma unroll
        for (int l = 0; l < 2; l++) {
            int idx = tid + l * 256;
            int row = idx >> 3, ch = idx & 7;
            int gr = m0 + row;
            uint32_t sa = aBase + st * SA_BYTES + (row * LDT + ch * 8) * 2;
            const __half* g = A + (size_t)(gr < M ? gr : 0) * K + kt * BKK + ch * 8;
            cp16(sa, g, gr < M);
        }
        // B: 128 rows x 8 chunks = 1024 tasks (4/thread)
#pragma unroll
        for (int l = 0; l < 4; l++) {
            int idx = tid + l * 256;
            int row = idx >> 3, ch = idx & 7;
            int gn = n0 + row;
            uint32_t sb = bBase + st * SB_BYTES + (row * LDT + ch * 8) * 2;
            const __half* g = B + (size_t)(gn < N ? gn : 0) * K + kt * BKK + ch * 8;
            cp16(sb, g, gn < N);
        }
        cp_commit();
    };

    load_stage(0, 0);

    int a_r = lane & 15;
    int a_c = (lane >> 4) * 8;
    int b_r = (lane & 7) + ((lane >> 4) << 3);
    int b_c = ((lane >> 3) & 1) * 8;

    for (int kt = 0; kt < nk; kt++) {
        int st = kt & 1;
        cp_wait0();
        __syncthreads();
        if (kt + 1 < nk) load_stage(st ^ 1, kt + 1);
        uint32_t sa = aBase + st * SA_BYTES;
        uint32_t sb = bBase + st * SB_BYTES;
#pragma unroll
        for (int ks = 0; ks < BKK; ks += 16) {
            uint32_t af[2][4];
#pragma unroll
            for (int im = 0; im < 2; im++)
                ldmx4(af[im], sa + ((m_base + im * 16 + a_r) * LDT + ks + a_c) * 2);
            uint32_t bf[2][4];
#pragma unroll
            for (int ib = 0; ib < 2; ib++)
                ldmx4(bf[ib], sb + ((n_base + ib * 16 + b_r) * LDT + ks + b_c) * 2);
#pragma unroll
            for (int im = 0; im < 2; im++)
#pragma unroll
                for (int jn = 0; jn < 4; jn++)
                    mma_fp16(acc[im][jn], af[im], bf[jn >> 1][(jn & 1) * 2], bf[jn >> 1][(jn & 1) * 2 + 1]);
        }
    }

#pragma unroll
    for (int im = 0; im < 2; im++) {
        int row0 = m0 + m_base + im * 16 + (lane >> 2);
#pragma unroll
        for (int jn = 0; jn < 4; jn++) {
            int col = n0 + n_base + jn * 8 + (lane & 3) * 2;
            if (col < N) {
                float bx = bias[col], by = bias[col + 1];
                if (row0 < M) {
                    __half2 o = __floats2half2_rn(acc[im][jn][0] + bx, acc[im][jn][1] + by);
                    *(__half2*)&C[(size_t)row0 * N + col] = o;
                }
                if (row0 + 8 < M) {
                    __half2 o = __floats2half2_rn(acc[im][jn][2] + bx, acc[im][jn][3] + by);
                    *(__half2*)&C[(size_t)(row0 + 8) * N + col] = o;
                }
            }
        }
    }
}

// ---------------- CSR build ----------------
__global__ void hist_kernel(const int* __restrict__ dst, int* __restrict__ deg) {
    int e = blockIdx.x * blockDim.x + threadIdx.x;
    if (e < NE) atomicAdd(&deg[dst[e]], 1);
}
__global__ void csr_scan_kernel(const int* __restrict__ deg, int* __restrict__ rowptr,
                                int* __restrict__ cursor) {
    __shared__ int part[1024];
    int t = threadIdx.x;
    int base = t * 10;
    int local[10];
    int s = 0;
#pragma unroll
    for (int i = 0; i < 10; i++) {
        int idx = base + i;
        local[i] = (idx < NN) ? deg[idx] : 0;
        s += local[i];
    }
    part[t] = s;
    __syncthreads();
    for (int off = 1; off < 1024; off <<= 1) {
        int v = (t >= off) ? part[t - off] : 0;
        __syncthreads();
        part[t] += v;
        __syncthreads();
    }
    int run = (t > 0) ? part[t - 1] : 0;
#pragma unroll
    for (int i = 0; i < 10; i++) {
        int idx = base + i;
        if (idx < NN) {
            rowptr[idx] = run;
            cursor[idx] = run;
            run += local[i];
        }
    }
    if (t == 1023) rowptr[NN] = run;
}
__global__ void scatter_kernel(const int* __restrict__ src, const int* __restrict__ dst,
                               int* __restrict__ cursor, int* __restrict__ psrc) {
    int e = blockIdx.x * blockDim.x + threadIdx.x;
    if (e < NE) {
        int pos = atomicAdd(&cursor[dst[e]], 1);
        psrc[pos] = src[e];
    }
}

// ---------------- fused attention + head-mean + skip + ELU (+ optional gate) ----------------
template <int CC>
__global__ void __launch_bounds__(256)
attn_combine_kernel(const __half* __restrict__ qkvs, int ld, int hc,
                    const int* __restrict__ rowptr, const int* __restrict__ psrc,
                    float* __restrict__ hout, __half* __restrict__ Anext, float scale,
                    const float* __restrict__ gw, const float* __restrict__ gb,
                    float* __restrict__ gatep) {
    extern __shared__ float sred[];  // [HH][CC]
    int n = blockIdx.x;
    int tid = threadIdx.x;
    int h = tid >> 5, lane = tid & 31;
    const __half* q = qkvs;
    const __half* k = qkvs + hc;
    const __half* v = qkvs + 2 * hc;
    const size_t qbase = (size_t)n * ld + (size_t)h * CC;
    int j0 = rowptr[n], j1 = rowptr[n + 1];
    float mmax = -INFINITY, den = 0.f;

    if constexpr (CC >= 256) {
        const int R = CC / 256;
        float qv[R][8], acc[R][8];
#pragma unroll
        for (int i = 0; i < R; i++) {
            uint4 t = *(const uint4*)(q + qbase + i * 256 + lane * 8);
            h8_to_f8(t, qv[i]);
#pragma unroll
            for (int j = 0; j < 8; j++) acc[i][j] = 0.f;
        }
        for (int j = j0; j < j1; j++) {
            int s = psrc[j];
            const size_t sb = (size_t)s * ld + (size_t)h * CC;
            float kf[R][8], vf[R][8];
#pragma unroll
            for (int i = 0; i < R; i++) {
                uint4 tk = *(const uint4*)(k + sb + i * 256 + lane * 8);
                uint4 tv = *(const uint4*)(v + sb + i * 256 + lane * 8);
                h8_to_f8(tk, kf[i]);
                h8_to_f8(tv, vf[i]);
            }
            float dot = 0.f;
#pragma unroll
            for (int i = 0; i < R; i++)
#pragma unroll
                for (int c = 0; c < 8; c++) dot = fmaf(qv[i][c], kf[i][c], dot);
#pragma unroll
            for (int o = 16; o; o >>= 1) dot += __shfl_xor_sync(0xFFFFFFFFu, dot, o);
            float a = dot * scale;
            float mnew = fmaxf(mmax, a);
            float corr = __expf(mmax - mnew);
            float wt = __expf(a - mnew);
            den = den * corr + wt;
#pragma unroll
            for (int i = 0; i < R; i++)
#pragma unroll
                for (int c = 0; c < 8; c++) acc[i][c] = fmaf(wt, vf[i][c], acc[i][c] * corr);
            mmax = mnew;
        }
        float inv = 1.f / fmaxf(den, 1e-16f);
#pragma unroll
        for (int i = 0; i < R; i++) {
            float4 o0 = make_float4(acc[i][0] * inv, acc[i][1] * inv, acc[i][2] * inv, acc[i][3] * inv);
            float4 o1 = make_float4(acc[i][4] * inv, acc[i][5] * inv, acc[i][6] * inv, acc[i][7] * inv);
            *(float4*)(sred + h * CC + i * 256 + lane * 8) = o0;
            *(float4*)(sred + h * CC + i * 256 + lane * 8 + 4) = o1;
        }
    } else {
        float2 qv = __half22float2(*(const __half2*)(q + qbase + lane * 2));
        float2 acc = make_float2(0.f, 0.f);
        for (int j = j0; j < j1; j++) {
            int s = psrc[j];
            const size_t sb = (size_t)s * ld + (size_t)h * CC;
            float2 kv = __half22float2(*(const __half2*)(k + sb + lane * 2));
            float2 vv = __half22float2(*(const __half2*)(v + sb + lane * 2));
            float dot = fmaf(qv.x, kv.x, qv.y * kv.y);
#pragma unroll
            for (int o = 16; o; o >>= 1) dot += __shfl_xor_sync(0xFFFFFFFFu, dot, o);
            float a = dot * scale;
            float mnew = fmaxf(mmax, a);
            float corr = __expf(mmax - mnew);
            float wt = __expf(a - mnew);
            den = den * corr + wt;
            acc.x = fmaf(wt, vv.x, acc.x * corr);
            acc.y = fmaf(wt, vv.y, acc.y * corr);
            mmax = mnew;
        }
        float inv = 1.f / fmaxf(den, 1e-16f);
        *(float2*)(sred + h * CC + lane * 2) = make_float2(acc.x * inv, acc.y * inv);
    }
    __syncthreads();

    const __half* skipp = qkvs + 3 * hc;
    float gacc = 0.f;
    for (int c = tid; c < CC; c += 256) {
        float s = 0.f;
#pragma unroll
        for (int h2 = 0; h2 < HH; h2++) s += sred[h2 * CC + c];
        float val = s * (1.f / HH) + __half2float(skipp[(size_t)n * ld + c]);
        val = val > 0.f ? val : expm1f(val);
        if (hout) hout[(size_t)n * CC + c] = val;
        if (Anext) Anext[(size_t)n * CC + c] = __float2half_rn(val);
        if (gatep) gacc = fmaf(val, gw[c], gacc);
    }
    if (gatep) {
        __syncthreads();
        sred[tid] = gacc;
        __syncthreads();
        for (int off = 128; off; off >>= 1) {
            if (tid < off) sred[tid] += sred[tid + off];
            __syncthreads();
        }
        if (tid == 0) gatep[n] = sred[0] + gb[0];
    }
}

// ---------------- fused pooling: one block per graph ----------------
__global__ void __launch_bounds__(256)
pool_all_kernel(const float* __restrict__ h, const float* __restrict__ gate,
                const int* __restrict__ batch, const float* __restrict__ fw,
                const float* __restrict__ fb, float* __restrict__ out) {
    __shared__ float red[256];
    __shared__ float spool[4][64];
    __shared__ float pool[64];
    __shared__ float sm, sd;
    int g = blockIdx.x;
    int tid = threadIdx.x;
    int lo = lbound(batch, NN, g);
    int hi = lbound(batch, NN, g + 1);

    float m = -INFINITY;
    for (int n = lo + tid; n < hi; n += 256) m = fmaxf(m, gate[n]);
    red[tid] = m;
    __syncthreads();
    for (int off = 128; off; off >>= 1) {
        if (tid < off) red[tid] = fmaxf(red[tid], red[tid + off]);
        __syncthreads();
    }
    if (tid == 0) sm = red[0];
    __syncthreads();
    float mm = sm;

    float s = 0.f;
    for (int n = lo + tid; n < hi; n += 256) s += expf(gate[n] - mm);
    red[tid] = s;
    __syncthreads();
    for (int off = 128; off; off >>= 1) {
        if (tid < off) red[tid] += red[tid + off];
        __syncthreads();
    }
    if (tid == 0) sd = fmaxf(red[0], 1e-16f);
    __syncthreads();
    float inv = 1.f / sd;

    int grp = tid >> 6, c = tid & 63;
    float acc = 0.f;
    for (int n = lo + grp; n < hi; n += 4) {
        float w = expf(gate[n] - mm) * inv;
        acc = fmaf(w, h[(size_t)n * 64 + c], acc);
    }
    spool[grp][c] = acc;
    __syncthreads();
    if (tid < 64) pool[tid] = spool[0][tid] + spool[1][tid] + spool[2][tid] + spool[3][tid];
    __syncthreads();

    if (tid < 10) {
        float o = fb[tid];
#pragma unroll
        for (int cc = 0; cc < 64; cc++) o = fmaf(pool[cc], fw[cc * 10 + tid], o);
        out[g * 10 + tid] = o;
    }
}

// ---------------- host side ----------------
struct Ptrs {
    __half* qkvs;
    float *hA, *gate, *biasp;
    __half *Ac, *Bc;
    int *deg, *rowptr, *cursor, *psrc;
};

static void layer_gemm(int fin, int C, const float* const* W, const Ptrs& P) {
    int hc = C * HH;
    int Ntot = 3 * hc + C;
    dim3 tg((fin + 31) / 32, (hc + 31) / 32, 4);
    convBT4_kernel<<<tg, dim3(32, 8)>>>(W[0], W[2], W[4], W[6], P.Bc, fin, hc, C);
    pack_bias_kernel<<<(Ntot + 255) / 256, 256>>>(W[1], W[3], W[5], W[7], hc, C, P.biasp);
    dim3 grid((Ntot + BN - 1) / BN, (NN + BM - 1) / BM);
    gemm_mma_kernel<<<grid, 256, GEMM_SMEM>>>(P.Ac, P.Bc, P.biasp, P.qkvs, NN, fin, Ntot);
}

static void layer_attn(int C, float* hout, __half* Anext,
                       const float* gw, const float* gb, float* gatep, const Ptrs& P) {
    int hc = C * HH;
    int Ntot = 3 * hc + C;
    float scale = 1.f / sqrtf((float)C);
    int smem = HH * C * sizeof(float);
    if (C == 512)
        attn_combine_kernel<512><<<NN, 256, smem>>>(P.qkvs, Ntot, hc, P.rowptr, P.psrc, hout, Anext, scale, gw, gb, gatep);
    else if (C == 256)
        attn_combine_kernel<256><<<NN, 256, smem>>>(P.qkvs, Ntot, hc, P.rowptr, P.psrc, hout, Anext, scale, gw, gb, gatep);
    else
        attn_combine_kernel<64><<<NN, 256, smem>>>(P.qkvs, Ntot, hc, P.rowptr, P.psrc, hout, Anext, scale, gw, gb, gatep);
}

extern "C" void kernel_launch(void* const* d_in, const int* in_sizes, int n_in,
                              void* d_out, int out_size) {
    const float* x     = (const float*)d_in[0];
    const int*   ei    = (const int*)d_in[1];
    const int*   batch = (const int*)d_in[2];
    const float* W[24];
    for (int i = 0; i < 24; i++) W[i] = (const float*)d_in[3 + i];
    const float* gate_w = (const float*)d_in[27];
    const float* gate_b = (const float*)d_in[28];
    const float* fc_w   = (const float*)d_in[29];
    const float* fc_b   = (const float*)d_in[30];
    float* out = (float*)d_out;

    const int* src = ei;
    const int* dst = ei + NE;

    cudaFuncSetAttribute(gemm_mma_kernel, cudaFuncAttributeMaxDynamicSharedMemorySize, GEMM_SMEM);

    Ptrs P;
    cudaGetSymbolAddress((void**)&P.qkvs, g_qkvs);
    cudaGetSymbolAddress((void**)&P.hA, g_hA);
    cudaGetSymbolAddress((void**)&P.gate, g_gate);
    cudaGetSymbolAddress((void**)&P.biasp, g_biasp);
    cudaGetSymbolAddress((void**)&P.Ac, g_Acomp);
    cudaGetSymbolAddress((void**)&P.Bc, g_Bcomp);
    cudaGetSymbolAddress((void**)&P.deg, g_deg);
    cudaGetSymbolAddress((void**)&P.rowptr, g_rowptr);
    cudaGetSymbolAddress((void**)&P.cursor, g_cursor);
    cudaGetSymbolAddress((void**)&P.psrc, g_psrc);

    size_t na = (size_t)NN * 128;
    convA_kernel<<<(unsigned)((na + 255) / 256), 256>>>(x, P.Ac, na);
    layer_gemm(128, 512, &W[0], P);

    fill_int_kernel<<<(NN + 255) / 256, 256>>>(P.deg, 0, NN);
    hist_kernel<<<(NE + 255) / 256, 256>>>(dst, P.deg);
    csr_scan_kernel<<<1, 1024>>>(P.deg, P.rowptr, P.cursor);
    scatter_kernel<<<(NE + 255) / 256, 256>>>(src, dst, P.cursor, P.psrc);

    layer_attn(512, nullptr, P.Ac, nullptr, nullptr, nullptr, P);

    layer_gemm(512, 256, &W[8], P);
    layer_attn(256, nullptr, P.Ac, nullptr, nullptr, nullptr, P);

    layer_gemm(256, 64, &W[16], P);
    layer_attn(64, P.hA, nullptr, gate_w, gate_b, P.gate, P);

    pool_all_kernel<<<NG, 256>>>(P.hA, P.gate, batch, fc_w, fc_b, out);
}

// round 16
// speedup vs baseline: 1.1090x; 1.1090x over previous
#include <cuda_runtime.h>
#include <cuda_fp16.h>
#include <math.h>
#include <stdint.h>

#define NN 10000
#define NE 30000
#define NG 50
#define HH 8
#define NTOT1 12800  // 3*4096+512

// ---------------- scratch (device globals) ----------------
__device__ __half g_qkvs[NN * NTOT1];
__device__ float g_hA[NN * 512];
__device__ float g_gate[NN];
__device__ float g_biasp[NTOT1];
__device__ __half g_Acomp[NN * 512];
__device__ __half g_Bcomp[6400 * 512];
__device__ int g_deg[NN];
__device__ int g_rowptr[NN + 1];
__device__ int g_cursor[NN];
__device__ int g_psrc[NE];   // src node id per CSR slot

// ---------------- helpers ----------------
__device__ __forceinline__ uint32_t smem_u32(const void* p) {
    uint32_t a;
    asm("{ .reg .u64 t; cvta.to.shared.u64 t, %1; cvt.u32.u64 %0, t; }" : "=r"(a) : "l"(p));
    return a;
}
__device__ __forceinline__ void cp16(uint32_t saddr, const void* g) {
    asm volatile("cp.async.cg.shared.global [%0], [%1], 16;" :: "r"(saddr), "l"(g));
}
__device__ __forceinline__ void cp16p(uint32_t saddr, const void* g, bool pred) {
    int sz = pred ? 16 : 0;
    asm volatile("cp.async.cg.shared.global [%0], [%1], 16, %2;" :: "r"(saddr), "l"(g), "r"(sz));
}
__device__ __forceinline__ void cp_commit() { asm volatile("cp.async.commit_group;"); }
__device__ __forceinline__ void cp_wait0() { asm volatile("cp.async.wait_group 0;"); }
__device__ __forceinline__ void ldmx4(uint32_t* r, uint32_t addr) {
    asm volatile("ldmatrix.sync.aligned.m8n8.x4.shared.b16 {%0,%1,%2,%3}, [%4];"
                 : "=r"(r[0]), "=r"(r[1]), "=r"(r[2]), "=r"(r[3]) : "r"(addr));
}
__device__ __forceinline__ void mma_fp16(float* c, const uint32_t* a, uint32_t b0, uint32_t b1) {
    asm volatile(
        "mma.sync.aligned.m16n8k16.row.col.f32.f16.f16.f32 "
        "{%0,%1,%2,%3}, {%4,%5,%6,%7}, {%8,%9}, {%0,%1,%2,%3};"
        : "+f"(c[0]), "+f"(c[1]), "+f"(c[2]), "+f"(c[3])
        : "r"(a[0]), "r"(a[1]), "r"(a[2]), "r"(a[3]), "r"(b0), "r"(b1));
}
__device__ __forceinline__ void h8_to_f8(uint4 t, float* f) {
    const __half2* hp = (const __half2*)&t;
#pragma unroll
    for (int j = 0; j < 4; j++) {
        float2 xy = __half22float2(hp[j]);
        f[2 * j] = xy.x;
        f[2 * j + 1] = xy.y;
    }
}
__device__ __forceinline__ int lbound(const int* a, int n, int key) {
    int lo = 0, hi = n;
    while (lo < hi) {
        int mid = (lo + hi) >> 1;
        if (a[mid] < key) lo = mid + 1;
        else hi = mid;
    }
    return lo;
}

// ---------------- utility kernels ----------------
__global__ void fill_int_kernel(int* p, int v, int n) {
    int i = blockIdx.x * blockDim.x + threadIdx.x;
    if (i < n) p[i] = v;
}

// ---------------- fp32 -> fp16 convert (vectorized) ----------------
__global__ void convA_kernel(const float* __restrict__ A, __half* __restrict__ out, size_t n4) {
    size_t i = (size_t)blockIdx.x * blockDim.x + threadIdx.x;
    if (i >= n4) return;
    float4 v = *(const float4*)(A + i * 4);
    __half2 h0 = __floats2half2_rn(v.x, v.y);
    __half2 h1 = __floats2half2_rn(v.z, v.w);
    *(__half2*)(out + i * 4) = h0;
    *(__half2*)(out + i * 4 + 2) = h1;
}

__global__ void convBT4_kernel(const float* __restrict__ qw, const float* __restrict__ kw,
                               const float* __restrict__ vw, const float* __restrict__ sw,
                               __half* __restrict__ out, int K, int hc, int C) {
    int z = blockIdx.z;
    const float* W = (z == 0) ? qw : (z == 1) ? kw : (z == 2) ? vw : sw;
    int N = (z < 3) ? hc : C;
    int rowOff = z * hc;
    __shared__ float t[32][33];
    int kb = blockIdx.x * 32, nb = blockIdx.y * 32;
    if (nb >= N) return;
    int tx = threadIdx.x, ty = threadIdx.y;  // 32 x 8
    for (int r = ty; r < 32; r += 8) {
        int kk = kb + r, nn2 = nb + tx;
        t[r][tx] = (kk < K && nn2 < N) ? W[(size_t)kk * N + nn2] : 0.f;
    }
    __syncthreads();
    for (int r = ty; r < 32; r += 8) {
        int nn2 = nb + r, kk = kb + tx;
        if (nn2 < N && kk < K)
            out[(size_t)(rowOff + nn2) * K + kk] = __float2half_rn(t[tx][r]);
    }
}

__global__ void pack_bias_kernel(const float* __restrict__ qb, const float* __restrict__ kb,
                                 const float* __restrict__ vb, const float* __restrict__ sb,
                                 int hc, int C, float* __restrict__ out) {
    int i = blockIdx.x * blockDim.x + threadIdx.x;
    int Ntot = 3 * hc + C;
    if (i >= Ntot) return;
    float v;
    if (i < hc) v = qb[i];
    else if (i < 2 * hc) v = kb[i - hc];
    else if (i < 3 * hc) v = vb[i - 2 * hc];
    else v = sb[i - 3 * hc];
    out[i] = v;
}

// ---------------- fp16 mma.sync GEMM: 128x128 tile, BKK=64, single-sync double buffer ----------------
// N is always a multiple of BN; only last M-strip needs predicates.
#define BM 128
#define BN 128
#define BKK 64
#define LDT 72
#define SA_BYTES (BM * LDT * 2)
#define SB_BYTES (BN * LDT * 2)
#define GEMM_SMEM (2 * (SA_BYTES + SB_BYTES))

__global__ void __launch_bounds__(256, 2)
gemm_mma_kernel(const __half* __restrict__ A, const __half* __restrict__ B,
                const float* __restrict__ bias, __half* __restrict__ C,
                int M, int K, int N) {
    extern __shared__ char smraw[];
    uint32_t aBase = smem_u32(smraw);
    uint32_t bBase = aBase + 2 * SA_BYTES;
    int tid = threadIdx.x;
    int lane = tid & 31, wid = tid >> 5;
    int m0 = blockIdx.y * BM, n0 = blockIdx.x * BN;
    int warp_m = wid & 3, warp_n = wid >> 2;  // 4 x 2
    int m_base = warp_m * 32, n_base = warp_n * 64;
    bool interior = (m0 + BM <= M);

    float acc[2][8][4];
#pragma unroll
    for (int i = 0; i < 2; i++)
#pragma unroll
        for (int j = 0; j < 8; j++)
#pragma unroll
            for (int r = 0; r < 4; r++) acc[i][j][r] = 0.f;

    int nk = K >> 6;  // K multiple of 64

    auto load_stage = [&](int st, int kt) {
        if (interior) {
#pragma unroll
            for (int l = 0; l < 4; l++) {
                int idx = tid + l * 256;
                int row = idx >> 3, ch = idx & 7;
                uint32_t sa = aBase + st * SA_BYTES + (row * LDT + ch * 8) * 2;
                cp16(sa, A + (size_t)(m0 + row) * K + kt * BKK + ch * 8);
            }
        } else {
#pragma unroll
            for (int l = 0; l < 4; l++) {
                int idx = tid + l * 256;
                int row = idx >> 3, ch = idx & 7;
                int gr = m0 + row;
                uint32_t sa = aBase + st * SA_BYTES + (row * LDT + ch * 8) * 2;
                cp16p(sa, A + (size_t)(gr < M ? gr : 0) * K + kt * BKK + ch * 8, gr < M);
            }
        }
#pragma unroll
        for (int l = 0; l < 4; l++) {
            int idx = tid + l * 256;
            int row = idx >> 3, ch = idx & 7;
            uint32_t sb = bBase + st * SB_BYTES + (row * LDT + ch * 8) * 2;
            cp16(sb, B + (size_t)(n0 + row) * K + kt * BKK + ch * 8);
        }
        cp_commit();
    };

    load_stage(0, 0);

    int a_r = lane & 15;
    int a_c = (lane >> 4) * 8;
    int b_r = (lane & 7) + ((lane >> 4) << 3);
    int b_c = ((lane >> 3) & 1) * 8;

    for (int kt = 0; kt < nk; kt++) {
        int st = kt & 1;
        cp_wait0();
        __syncthreads();
        if (kt + 1 < nk) load_stage(st ^ 1, kt + 1);
        uint32_t sa = aBase + st * SA_BYTES;
        uint32_t sb = bBase + st * SB_BYTES;
#pragma unroll
        for (int ks = 0; ks < BKK; ks += 16) {
            uint32_t af[2][4];
#pragma unroll
            for (int im = 0; im < 2; im++)
                ldmx4(af[im], sa + ((m_base + im * 16 + a_r) * LDT + ks + a_c) * 2);
            uint32_t bf[4][4];
#pragma unroll
            for (int ib = 0; ib < 4; ib++)
                ldmx4(bf[ib], sb + ((n_base + ib * 16 + b_r) * LDT + ks + b_c) * 2);
#pragma unroll
            for (int im = 0; im < 2; im++)
#pragma unroll
                for (int jn = 0; jn < 8; jn++)
                    mma_fp16(acc[im][jn], af[im], bf[jn >> 1][(jn & 1) * 2], bf[jn >> 1][(jn & 1) * 2 + 1]);
        }
    }

#pragma unroll
    for (int im = 0; im < 2; im++) {
        int row0 = m0 + m_base + im * 16 + (lane >> 2);
#pragma unroll
        for (int jn = 0; jn < 8; jn++) {
            int col = n0 + n_base + jn * 8 + (lane & 3) * 2;
            float bx = bias[col], by = bias[col + 1];
            if (row0 < M) {
                __half2 o = __floats2half2_rn(acc[im][jn][0] + bx, acc[im][jn][1] + by);
                *(__half2*)&C[(size_t)row0 * N + col] = o;
            }
            if (row0 + 8 < M) {
                __half2 o = __floats2half2_rn(acc[im][jn][2] + bx, acc[im][jn][3] + by);
                *(__half2*)&C[(size_t)(row0 + 8) * N + col] = o;
            }
        }
    }
}

// ---------------- CSR build ----------------
__global__ void hist_kernel(const int* __restrict__ dst, int* __restrict__ deg) {
    int e = blockIdx.x * blockDim.x + threadIdx.x;
    if (e < NE) atomicAdd(&deg[dst[e]], 1);
}
__global__ void csr_scan_kernel(const int* __restrict__ deg, int* __restrict__ rowptr,
                                int* __restrict__ cursor) {
    __shared__ int part[1024];
    int t = threadIdx.x;
    int base = t * 10;
    int local[10];
    int s = 0;
#pragma unroll
    for (int i = 0; i < 10; i++) {
        int idx = base + i;
        local[i] = (idx < NN) ? deg[idx] : 0;
        s += local[i];
    }
    part[t] = s;
    __syncthreads();
    for (int off = 1; off < 1024; off <<= 1) {
        int v = (t >= off) ? part[t - off] : 0;
        __syncthreads();
        part[t] += v;
        __syncthreads();
    }
    int run = (t > 0) ? part[t - 1] : 0;
#pragma unroll
    for (int i = 0; i < 10; i++) {
        int idx = base + i;
        if (idx < NN) {
            rowptr[idx] = run;
            cursor[idx] = run;
            run += local[i];
        }
    }
    if (t == 1023) rowptr[NN] = run;
}
__global__ void scatter_kernel(const int* __restrict__ src, const int* __restrict__ dst,
                               int* __restrict__ cursor, int* __restrict__ psrc) {
    int e = blockIdx.x * blockDim.x + threadIdx.x;
    if (e < NE) {
        int pos = atomicAdd(&cursor[dst[e]], 1);
        psrc[pos] = src[e];
    }
}

// ---------------- fused attention + head-mean + skip + ELU (+ compile-time gate) ----------------
template <int CC, bool GATE>
__global__ void __launch_bounds__(256)
attn_combine_kernel(const __half* __restrict__ qkvs, int ld, int hc,
                    const int* __restrict__ rowptr, const int* __restrict__ psrc,
                    float* __restrict__ hout, __half* __restrict__ Anext, float scale,
                    const float* __restrict__ gw, const float* __restrict__ gb,
                    float* __restrict__ gatep) {
    extern __shared__ float sred[];  // [HH][CC]
    int n = blockIdx.x;
    int tid = threadIdx.x;
    int h = tid >> 5, lane = tid & 31;
    const __half* q = qkvs;
    const __half* k = qkvs + hc;
    const __half* v = qkvs + 2 * hc;
    const size_t qbase = (size_t)n * ld + (size_t)h * CC;
    int j0 = rowptr[n], j1 = rowptr[n + 1];
    float mmax = -INFINITY, den = 0.f;

    if constexpr (CC >= 256) {
        const int R = CC / 256;
        float qv[R][8], acc[R][8];
#pragma unroll
        for (int i = 0; i < R; i++) {
            uint4 t = *(const uint4*)(q + qbase + i * 256 + lane * 8);
            h8_to_f8(t, qv[i]);
#pragma unroll
            for (int j = 0; j < 8; j++) acc[i][j] = 0.f;
        }
        for (int j = j0; j < j1; j++) {
            int s = psrc[j];
            const size_t sb = (size_t)s * ld + (size_t)h * CC;
            float kf[R][8], vf[R][8];
#pragma unroll
            for (int i = 0; i < R; i++) {
                uint4 tk = *(const uint4*)(k + sb + i * 256 + lane * 8);
                uint4 tv = *(const uint4*)(v + sb + i * 256 + lane * 8);
                h8_to_f8(tk, kf[i]);
                h8_to_f8(tv, vf[i]);
            }
            float dot = 0.f;
#pragma unroll
            for (int i = 0; i < R; i++)
#pragma unroll
                for (int c = 0; c < 8; c++) dot = fmaf(qv[i][c], kf[i][c], dot);
#pragma unroll
            for (int o = 16; o; o >>= 1) dot += __shfl_xor_sync(0xFFFFFFFFu, dot, o);
            float a = dot * scale;
            float mnew = fmaxf(mmax, a);
            float corr = __expf(mmax - mnew);
            float wt = __expf(a - mnew);
            den = den * corr + wt;
#pragma unroll
            for (int i = 0; i < R; i++)
#pragma unroll
                for (int c = 0; c < 8; c++) acc[i][c] = fmaf(wt, vf[i][c], acc[i][c] * corr);
            mmax = mnew;
        }
        float inv = 1.f / fmaxf(den, 1e-16f);
#pragma unroll
        for (int i = 0; i < R; i++) {
            float4 o0 = make_float4(acc[i][0] * inv, acc[i][1] * inv, acc[i][2] * inv, acc[i][3] * inv);
            float4 o1 = make_float4(acc[i][4] * inv, acc[i][5] * inv, acc[i][6] * inv, acc[i][7] * inv);
            *(float4*)(sred + h * CC + i * 256 + lane * 8) = o0;
            *(float4*)(sred + h * CC + i * 256 + lane * 8 + 4) = o1;
        }
    } else {
        float2 qv = __half22float2(*(const __half2*)(q + qbase + lane * 2));
        float2 acc = make_float2(0.f, 0.f);
        for (int j = j0; j < j1; j++) {
            int s = psrc[j];
            const size_t sb = (size_t)s * ld + (size_t)h * CC;
            float2 kv = __half22float2(*(const __half2*)(k + sb + lane * 2));
            float2 vv = __half22float2(*(const __half2*)(v + sb + lane * 2));
            float dot = fmaf(qv.x, kv.x, qv.y * kv.y);
#pragma unroll
            for (int o = 16; o; o >>= 1) dot += __shfl_xor_sync(0xFFFFFFFFu, dot, o);
            float a = dot * scale;
            float mnew = fmaxf(mmax, a);
            float corr = __expf(mmax - mnew);
            float wt = __expf(a - mnew);
            den = den * corr + wt;
            acc.x = fmaf(wt, vv.x, acc.x * corr);
            acc.y = fmaf(wt, vv.y, acc.y * corr);
            mmax = mnew;
        }
        float inv = 1.f / fmaxf(den, 1e-16f);
        *(float2*)(sred + h * CC + lane * 2) = make_float2(acc.x * inv, acc.y * inv);
    }
    __syncthreads();

    const __half* skipp = qkvs + 3 * hc;
    float gacc = 0.f;
    for (int c = tid; c < CC; c += 256) {
        float s = 0.f;
#pragma unroll
        for (int h2 = 0; h2 < HH; h2++) s += sred[h2 * CC + c];
        float val = s * (1.f / HH) + __half2float(skipp[(size_t)n * ld + c]);
        val = val > 0.f ? val : expm1f(val);
        if constexpr (GATE) {
            hout[(size_t)n * CC + c] = val;
            gacc = fmaf(val, gw[c], gacc);
        } else {
            Anext[(size_t)n * CC + c] = __float2half_rn(val);
        }
    }
    if constexpr (GATE) {
        __syncthreads();
        sred[tid] = gacc;
        __syncthreads();
        for (int off = 128; off; off >>= 1) {
            if (tid < off) sred[tid] += sred[tid + off];
            __syncthreads();
        }
        if (tid == 0) gatep[n] = sred[0] + gb[0];
    }
}

// ---------------- fused pooling: one block per graph ----------------
__global__ void __launch_bounds__(256)
pool_all_kernel(const float* __restrict__ h, const float* __restrict__ gate,
                const int* __restrict__ batch, const float* __restrict__ fw,
                const float* __restrict__ fb, float* __restrict__ out) {
    __shared__ float red[256];
    __shared__ float spool[4][64];
    __shared__ float pool[64];
    __shared__ float sm, sd;
    int g = blockIdx.x;
    int tid = threadIdx.x;
    int lo = lbound(batch, NN, g);
    int hi = lbound(batch, NN, g + 1);

    float m = -INFINITY;
    for (int n = lo + tid; n < hi; n += 256) m = fmaxf(m, gate[n]);
    red[tid] = m;
    __syncthreads();
    for (int off = 128; off; off >>= 1) {
        if (tid < off) red[tid] = fmaxf(red[tid], red[tid + off]);
        __syncthreads();
    }
    if (tid == 0) sm = red[0];
    __syncthreads();
    float mm = sm;

    float s = 0.f;
    for (int n = lo + tid; n < hi; n += 256) s += expf(gate[n] - mm);
    red[tid] = s;
    __syncthreads();
    for (int off = 128; off; off >>= 1) {
        if (tid < off) red[tid] += red[tid + off];
        __syncthreads();
    }
    if (tid == 0) sd = fmaxf(red[0], 1e-16f);
    __syncthreads();
    float inv = 1.f / sd;

    int grp = tid >> 6, c = tid & 63;
    float acc = 0.f;
    for (int n = lo + grp; n < hi; n += 4) {
        float w = expf(gate[n] - mm) * inv;
        acc = fmaf(w, h[(size_t)n * 64 + c], acc);
    }
    spool[grp][c] = acc;
    __syncthreads();
    if (tid < 64) pool[tid] = spool[0][tid] + spool[1][tid] + spool[2][tid] + spool[3][tid];
    __syncthreads();

    if (tid < 10) {
        float o = fb[tid];
#pragma unroll
        for (int cc = 0; cc < 64; cc++) o = fmaf(pool[cc], fw[cc * 10 + tid], o);
        out[g * 10 + tid] = o;
    }
}

// ---------------- host side ----------------
struct Ptrs {
    __half* qkvs;
    float *hA, *gate, *biasp;
    __half *Ac, *Bc;
    int *deg, *rowptr, *cursor, *psrc;
};

static void layer_gemm(int fin, int C, const float* const* W, const Ptrs& P) {
    int hc = C * HH;
    int Ntot = 3 * hc + C;
    dim3 tg((fin + 31) / 32, (hc + 31) / 32, 4);
    convBT4_kernel<<<tg, dim3(32, 8)>>>(W[0], W[2], W[4], W[6], P.Bc, fin, hc, C);
    pack_bias_kernel<<<(Ntot + 255) / 256, 256>>>(W[1], W[3], W[5], W[7], hc, C, P.biasp);
    dim3 grid((Ntot + BN - 1) / BN, (NN + BM - 1) / BM);
    gemm_mma_kernel<<<grid, 256, GEMM_SMEM>>>(P.Ac, P.Bc, P.biasp, P.qkvs, NN, fin, Ntot);
}

static void layer_attn(int C, float* hout, __half* Anext,
                       const float* gw, const float* gb, float* gatep, const Ptrs& P) {
    int hc = C * HH;
    int Ntot = 3 * hc + C;
    float scale = 1.f / sqrtf((float)C);
    int smem = HH * C * sizeof(float);
    if (C == 512)
        attn_combine_kernel<512, false><<<NN, 256, smem>>>(P.qkvs, Ntot, hc, P.rowptr, P.psrc, hout, Anext, scale, gw, gb, gatep);
    else if (C == 256)
        attn_combine_kernel<256, false><<<NN, 256, smem>>>(P.qkvs, Ntot, hc, P.rowptr, P.psrc, hout, Anext, scale, gw, gb, gatep);
    else
        attn_combine_kernel<64, true><<<NN, 256, smem>>>(P.qkvs, Ntot, hc, P.rowptr, P.psrc, hout, Anext, scale, gw, gb, gatep);
}

extern "C" void kernel_launch(void* const* d_in, const int* in_sizes, int n_in,
                              void* d_out, int out_size) {
    const float* x     = (const float*)d_in[0];
    const int*   ei    = (const int*)d_in[1];
    const int*   batch = (const int*)d_in[2];
    const float* W[24];
    for (int i = 0; i < 24; i++) W[i] = (const float*)d_in[3 + i];
    const float* gate_w = (const float*)d_in[27];
    const float* gate_b = (const float*)d_in[28];
    const float* fc_w   = (const float*)d_in[29];
    const float* fc_b   = (const float*)d_in[30];
    float* out = (float*)d_out;

    const int* src = ei;
    const int* dst = ei + NE;

    cudaFuncSetAttribute(gemm_mma_kernel, cudaFuncAttributeMaxDynamicSharedMemorySize, GEMM_SMEM);

    Ptrs P;
    cudaGetSymbolAddress((void**)&P.qkvs, g_qkvs);
    cudaGetSymbolAddress((void**)&P.hA, g_hA);
    cudaGetSymbolAddress((void**)&P.gate, g_gate);
    cudaGetSymbolAddress((void**)&P.biasp, g_biasp);
    cudaGetSymbolAddress((void**)&P.Ac, g_Acomp);
    cudaGetSymbolAddress((void**)&P.Bc, g_Bcomp);
    cudaGetSymbolAddress((void**)&P.deg, g_deg);
    cudaGetSymbolAddress((void**)&P.rowptr, g_rowptr);
    cudaGetSymbolAddress((void**)&P.cursor, g_cursor);
    cudaGetSymbolAddress((void**)&P.psrc, g_psrc);

    // CSR build first (tiny kernels, clears the way for the layer pipeline)
    fill_int_kernel<<<(NN + 255) / 256, 256>>>(P.deg, 0, NN);
    hist_kernel<<<(NE + 255) / 256, 256>>>(dst, P.deg);
    csr_scan_kernel<<<1, 1024>>>(P.deg, P.rowptr, P.cursor);
    scatter_kernel<<<(NE + 255) / 256, 256>>>(src, dst, P.cursor, P.psrc);

    size_t na4 = (size_t)NN * 128 / 4;
    convA_kernel<<<(unsigned)((na4 + 255) / 256), 256>>>(x, P.Ac, na4);
    layer_gemm(128, 512, &W[0], P);
    layer_attn(512, nullptr, P.Ac, nullptr, nullptr, nullptr, P);

    layer_gemm(512, 256, &W[8], P);
    layer_attn(256, nullptr, P.Ac, nullptr, nullptr, nullptr, P);

    layer_gemm(256, 64, &W[16], P);
    layer_attn(64, P.hA, nullptr, gate_w, gate_b, P.gate, P);

    pool_all_kernel<<<NG, 256>>>(P.hA, P.gate, batch, fc_w, fc_b, out);
}